// round 1
// baseline (speedup 1.0000x reference)
#include <cuda_runtime.h>

// Problem constants
#define DIN   128
#define DOUT  128
#define DEG   48
#define KSEL  32
#define NPAD  50048   // 391 * 128, padded row count for GEMM tile stores

// Scratch for x = feat @ W  (25.7 MB static device array; allocation-free rule)
__device__ float g_x[(size_t)NPAD * DOUT];

// ---------------------------------------------------------------------------
// Kernel A: x = feat @ W   (50000 x 128 x 128), register-tiled SGEMM
// CTA: 256 threads, tile 128(M) x 128(N), k-tile 16, micro-tile 8x8
// ---------------------------------------------------------------------------
__global__ __launch_bounds__(256) void gemm_kernel(const float* __restrict__ feat,
                                                   const float* __restrict__ W,
                                                   int n)
{
    __shared__ __align__(16) float As[16][132];  // transposed A tile, padded pitch
    __shared__ __align__(16) float Bs[16][128];

    const int tid  = threadIdx.x;
    const int tx   = tid & 15;        // 0..15 -> 8 output cols each
    const int ty   = tid >> 4;        // 0..15 -> 8 output rows each
    const int row0 = blockIdx.x * 128;

    float acc[8][8];
#pragma unroll
    for (int i = 0; i < 8; ++i)
#pragma unroll
        for (int j = 0; j < 8; ++j) acc[i][j] = 0.0f;

    for (int kk = 0; kk < 128; kk += 16) {
        // Load A tile (128 rows x 16 k), store transposed As[k][m]
#pragma unroll
        for (int it = 0; it < 2; ++it) {
            int r  = tid & 127;
            int kq = (tid >> 7) + it * 2;           // float4 quad index 0..3
            int rg = row0 + r;
            if (rg > n - 1) rg = n - 1;             // clamp reads (outputs unused rows go to pad)
            float4 v = *(const float4*)&feat[(size_t)rg * DIN + kk + kq * 4];
            As[kq * 4 + 0][r] = v.x;
            As[kq * 4 + 1][r] = v.y;
            As[kq * 4 + 2][r] = v.z;
            As[kq * 4 + 3][r] = v.w;
        }
        // Load B tile (16 k x 128 n)
#pragma unroll
        for (int it = 0; it < 2; ++it) {
            int idx = tid + it * 256;               // 0..511
            int kl  = idx >> 5;                     // 0..15
            int c4  = idx & 31;                     // float4 col index
            *(float4*)&Bs[kl][c4 * 4] =
                *(const float4*)&W[(size_t)(kk + kl) * DOUT + c4 * 4];
        }
        __syncthreads();

#pragma unroll
        for (int k = 0; k < 16; ++k) {
            float a[8], b[8];
            *(float4*)&a[0] = *(const float4*)&As[k][ty * 8];
            *(float4*)&a[4] = *(const float4*)&As[k][ty * 8 + 4];
            *(float4*)&b[0] = *(const float4*)&Bs[k][tx * 8];
            *(float4*)&b[4] = *(const float4*)&Bs[k][tx * 8 + 4];
#pragma unroll
            for (int i = 0; i < 8; ++i)
#pragma unroll
                for (int j = 0; j < 8; ++j)
                    acc[i][j] = fmaf(a[i], b[j], acc[i][j]);
        }
        __syncthreads();
    }

    // Store (g_x is padded to NPAD rows, so no guard needed)
#pragma unroll
    for (int i = 0; i < 8; ++i) {
        int rg = row0 + ty * 8 + i;
        float4 v0 = make_float4(acc[i][0], acc[i][1], acc[i][2], acc[i][3]);
        float4 v1 = make_float4(acc[i][4], acc[i][5], acc[i][6], acc[i][7]);
        *(float4*)&g_x[(size_t)rg * DOUT + tx * 8 + 0] = v0;
        *(float4*)&g_x[(size_t)rg * DOUT + tx * 8 + 4] = v1;
    }
}

// ---------------------------------------------------------------------------
// Kernel B: per-node top-k selection, Gram, soft-medoid softmax, aggregation
// 1 CTA per node, 128 threads (4 warps)
// ---------------------------------------------------------------------------
__global__ __launch_bounds__(128) void node_kernel(const float* __restrict__ ew,
                                                   const int*   __restrict__ nbr,
                                                   const float* __restrict__ bias,
                                                   float*       __restrict__ out,
                                                   int n)
{
    __shared__ __align__(16) float sxi[32 * 132];   // xi rows, pitch 132 floats
    __shared__ float sg[32 * 33];                   // gram, pitch 33
    __shared__ float sw49[52];
    __shared__ int   sid49[52];
    __shared__ float selw[32];
    __shared__ int   selid[32];
    __shared__ float ssq[32];
    __shared__ float sdist[32];
    __shared__ float srel[32];

    const int node = blockIdx.x;
    const int tid  = threadIdx.x;
    const int lane = tid & 31;
    const int wrp  = tid >> 5;

    // --- load 48 edges + self-loop ---
    if (tid < DEG) {
        sw49[tid]  = ew[(size_t)node * DEG + tid];
        sid49[tid] = nbr[(size_t)node * DEG + tid];
    } else if (tid == DEG) {
        sw49[DEG]  = 1.0f;
        sid49[DEG] = node;
    }
    __syncthreads();

    // --- top-32 of 49 by weight (stable rank, matches lax.top_k tie-break) ---
    if (tid < DEG + 1) {
        float v = sw49[tid];
        int rank = 0;
#pragma unroll
        for (int j = 0; j < DEG + 1; ++j) {
            float wj = sw49[j];
            rank += (wj > v) || (wj == v && j < tid);
        }
        if (rank < KSEL) {
            selw[rank]  = v;
            selid[rank] = sid49[tid];
        }
    }
    __syncthreads();

    // --- gather xi = x[sel] into shared (32 rows x 128, pitch 132) ---
    {
        int k = tid >> 2, q = tid & 3;
        const float4* src = (const float4*)&g_x[(size_t)selid[k] * DOUT + q * 32];
        float4*       dst = (float4*)&sxi[k * 132 + q * 32];
#pragma unroll
        for (int i = 0; i < 8; ++i) dst[i] = src[i];
    }
    __syncthreads();

    // --- Gram: warp wrp computes rows a in [8*wrp, 8*wrp+8), lane = b ---
    {
        const int a0 = wrp * 8;
        float acc[8];
#pragma unroll
        for (int j = 0; j < 8; ++j) acc[j] = 0.0f;

#pragma unroll 4
        for (int d4 = 0; d4 < 32; ++d4) {
            float4 vb = *(const float4*)&sxi[lane * 132 + d4 * 4];
#pragma unroll
            for (int j = 0; j < 8; ++j) {
                float4 va = *(const float4*)&sxi[(a0 + j) * 132 + d4 * 4];
                acc[j] = fmaf(va.x, vb.x, acc[j]);
                acc[j] = fmaf(va.y, vb.y, acc[j]);
                acc[j] = fmaf(va.z, vb.z, acc[j]);
                acc[j] = fmaf(va.w, vb.w, acc[j]);
            }
        }
#pragma unroll
        for (int j = 0; j < 8; ++j) {
            sg[(a0 + j) * 33 + lane] = acc[j];
            if (lane == a0 + j) ssq[lane] = acc[j];   // diagonal = ||xi_a||^2
        }
    }
    __syncthreads();

    // --- weighted medoid distances: dist[a] = sum_b tw[b] * sqrt(max(d2,0)) ---
    {
        int a = tid >> 2, q = tid & 3;
        float sqa  = ssq[a];
        float part = 0.0f;
#pragma unroll
        for (int i = 0; i < 8; ++i) {
            int b = q * 8 + i;
            float d2 = sqa + ssq[b] - 2.0f * sg[a * 33 + b];
            float dm = (d2 > 0.0f) ? sqrtf(d2) : 0.0f;
            part = fmaf(selw[b], dm, part);
        }
        part += __shfl_down_sync(0xffffffffu, part, 2);
        part += __shfl_down_sync(0xffffffffu, part, 1);
        if (q == 0) sdist[a] = part;
    }
    __syncthreads();

    // --- softmax(-dist) * tw, renormalized (warp 0 only) ---
    if (tid < 32) {
        float v = sdist[tid];
        float m = v;
#pragma unroll
        for (int off = 16; off; off >>= 1)
            m = fminf(m, __shfl_xor_sync(0xffffffffu, m, off));
        float r = expf(m - v) * selw[tid];
        float s = r;
#pragma unroll
        for (int off = 16; off; off >>= 1)
            s += __shfl_xor_sync(0xffffffffu, s, off);
        srel[tid] = r / s;
    }
    __syncthreads();

    // --- out[d] = bias[d] + sum_k rel[k] * xi[k][d] ---
    {
        float acc = bias[tid];
#pragma unroll
        for (int k = 0; k < 32; ++k)
            acc = fmaf(srel[k], sxi[k * 132 + tid], acc);
        out[(size_t)node * DOUT + tid] = acc;
    }
}

// ---------------------------------------------------------------------------
// Launch
// ---------------------------------------------------------------------------
extern "C" void kernel_launch(void* const* d_in, const int* in_sizes, int n_in,
                              void* d_out, int out_size)
{
    const float* feat   = (const float*)d_in[0];   // [n, 128]
    const float* ew     = (const float*)d_in[1];   // [n, 48]
    const float* weight = (const float*)d_in[2];   // [128, 128]
    const float* bias   = (const float*)d_in[3];   // [128]
    const int*   nbr    = (const int*)  d_in[4];   // [n, 48] int32
    float*       out    = (float*)d_out;

    int n = in_sizes[0] / DIN;                     // 50000

    gemm_kernel<<<(n + 127) / 128, 256>>>(feat, weight, n);
    node_kernel<<<n, 128>>>(ew, nbr, bias, out, n);
}

// round 2
// speedup vs baseline: 1.3629x; 1.3629x over previous
#include <cuda_runtime.h>

// Problem constants
#define DIN   128
#define DOUT  128
#define DEG   48
#define KSEL  32
#define NPAD  50048   // padded row count for GEMM tile stores
#define PITCH 132     // sxi row pitch in floats (132*4 = 528 B, 16B-aligned, conflict-free)

// Scratch for x = feat @ W
__device__ float g_x[(size_t)NPAD * DOUT];

// Packed dual-FMA (sm_103a): d = a*b + c elementwise on two packed f32
#define FMA2(d, a, b, c) \
    asm("fma.rn.f32x2 %0, %1, %2, %3;" : "=l"(d) : "l"(a), "l"(b), "l"(c))

// ---------------------------------------------------------------------------
// Kernel A: x = feat @ W   (50000 x 128 x 128), register-tiled SGEMM, f32x2
// ---------------------------------------------------------------------------
__global__ __launch_bounds__(256) void gemm_kernel(const float* __restrict__ feat,
                                                   const float* __restrict__ W,
                                                   int n)
{
    __shared__ __align__(16) float As[16][132];
    __shared__ __align__(16) float Bs[16][128];

    const int tid  = threadIdx.x;
    const int tx   = tid & 15;
    const int ty   = tid >> 4;
    const int row0 = blockIdx.x * 128;

    unsigned long long acc2[8][4];
#pragma unroll
    for (int i = 0; i < 8; ++i)
#pragma unroll
        for (int j = 0; j < 4; ++j) acc2[i][j] = 0ull;

    for (int kk = 0; kk < 128; kk += 16) {
#pragma unroll
        for (int it = 0; it < 2; ++it) {
            int r  = tid & 127;
            int kq = (tid >> 7) + it * 2;
            int rg = row0 + r;
            if (rg > n - 1) rg = n - 1;
            float4 v = *(const float4*)&feat[(size_t)rg * DIN + kk + kq * 4];
            As[kq * 4 + 0][r] = v.x;
            As[kq * 4 + 1][r] = v.y;
            As[kq * 4 + 2][r] = v.z;
            As[kq * 4 + 3][r] = v.w;
        }
#pragma unroll
        for (int it = 0; it < 2; ++it) {
            int idx = tid + it * 256;
            int kl  = idx >> 5;
            int c4  = idx & 31;
            *(float4*)&Bs[kl][c4 * 4] =
                *(const float4*)&W[(size_t)(kk + kl) * DOUT + c4 * 4];
        }
        __syncthreads();

#pragma unroll
        for (int k = 0; k < 16; ++k) {
            float a[8];
            *(float4*)&a[0] = *(const float4*)&As[k][ty * 8];
            *(float4*)&a[4] = *(const float4*)&As[k][ty * 8 + 4];
            ulonglong2 b01 = *(const ulonglong2*)&Bs[k][tx * 8];
            ulonglong2 b23 = *(const ulonglong2*)&Bs[k][tx * 8 + 4];
#pragma unroll
            for (int i = 0; i < 8; ++i) {
                unsigned long long ai;
                asm("mov.b64 %0, {%1, %1};" : "=l"(ai) : "f"(a[i]));
                FMA2(acc2[i][0], ai, b01.x, acc2[i][0]);
                FMA2(acc2[i][1], ai, b01.y, acc2[i][1]);
                FMA2(acc2[i][2], ai, b23.x, acc2[i][2]);
                FMA2(acc2[i][3], ai, b23.y, acc2[i][3]);
            }
        }
        __syncthreads();
    }

#pragma unroll
    for (int i = 0; i < 8; ++i) {
        int rg = row0 + ty * 8 + i;
        float o[8];
#pragma unroll
        for (int j = 0; j < 4; ++j)
            asm("mov.b64 {%0, %1}, %2;" : "=f"(o[2 * j]), "=f"(o[2 * j + 1]) : "l"(acc2[i][j]));
        *(float4*)&g_x[(size_t)rg * DOUT + tx * 8 + 0] = *(float4*)&o[0];
        *(float4*)&g_x[(size_t)rg * DOUT + tx * 8 + 4] = *(float4*)&o[4];
    }
}

// ---------------------------------------------------------------------------
// Kernel B: per-node top-k, Gram (f32x2), soft-medoid softmax, aggregation
// 1 CTA per node, 128 threads (4 warps)
// ---------------------------------------------------------------------------
__global__ __launch_bounds__(128) void node_kernel(const float* __restrict__ ew,
                                                   const int*   __restrict__ nbr,
                                                   const float* __restrict__ bias,
                                                   float*       __restrict__ out,
                                                   int n)
{
    __shared__ __align__(16) float sxi[32 * PITCH];
    __shared__ float sg[32 * 33];
    __shared__ float sw49[52];
    __shared__ int   sid49[52];
    __shared__ float selw[32];
    __shared__ int   selid[32];
    __shared__ float ssq[32];
    __shared__ float sdist[32];
    __shared__ float srel[32];

    const int node = blockIdx.x;
    const int tid  = threadIdx.x;
    const int lane = tid & 31;
    const int wrp  = tid >> 5;

    // --- load 48 edges + self-loop ---
    if (tid < DEG) {
        sw49[tid]  = ew[(size_t)node * DEG + tid];
        sid49[tid] = nbr[(size_t)node * DEG + tid];
    } else if (tid == DEG) {
        sw49[DEG]  = 1.0f;
        sid49[DEG] = node;
    }
    __syncthreads();

    // --- top-32 of 49 by weight (stable rank, matches lax.top_k tie-break) ---
    if (tid < DEG + 1) {
        float v = sw49[tid];
        int rank = 0;
#pragma unroll
        for (int j = 0; j < DEG + 1; ++j) {
            float wj = sw49[j];
            rank += (wj > v) || (wj == v && j < tid);
        }
        if (rank < KSEL) {
            selw[rank]  = v;
            selid[rank] = sid49[tid];
        }
    }
    __syncthreads();

    // --- gather xi = x[sel] into shared, coalesced: warp loads whole rows ---
    {
        const int r0 = wrp * 8;
        float4 v[8];
#pragma unroll
        for (int r = 0; r < 8; ++r) {
            int id = selid[r0 + r];
            v[r] = *(const float4*)&g_x[(size_t)id * DOUT + lane * 4];
        }
#pragma unroll
        for (int r = 0; r < 8; ++r)
            *(float4*)&sxi[(r0 + r) * PITCH + lane * 4] = v[r];
    }
    __syncthreads();

    // --- Gram via packed f32x2: warp wrp computes rows [8w, 8w+8), lane = b ---
    {
        const int a0 = wrp * 8;
        unsigned long long acc2[8];
#pragma unroll
        for (int j = 0; j < 8; ++j) acc2[j] = 0ull;

#pragma unroll 4
        for (int d4 = 0; d4 < 32; ++d4) {
            ulonglong2 vb = *(const ulonglong2*)&sxi[lane * PITCH + d4 * 4];
#pragma unroll
            for (int j = 0; j < 8; ++j) {
                ulonglong2 va = *(const ulonglong2*)&sxi[(a0 + j) * PITCH + d4 * 4];
                FMA2(acc2[j], va.x, vb.x, acc2[j]);
                FMA2(acc2[j], va.y, vb.y, acc2[j]);
            }
        }
#pragma unroll
        for (int j = 0; j < 8; ++j) {
            float lo, hi;
            asm("mov.b64 {%0, %1}, %2;" : "=f"(lo), "=f"(hi) : "l"(acc2[j]));
            float g = lo + hi;
            sg[(a0 + j) * 33 + lane] = g;
            if (lane == a0 + j) ssq[lane] = g;   // diagonal = ||xi_a||^2
        }
    }
    __syncthreads();

    // --- weighted medoid distances ---
    {
        int a = tid >> 2, q = tid & 3;
        float sqa  = ssq[a];
        float part = 0.0f;
#pragma unroll
        for (int i = 0; i < 8; ++i) {
            int b = q * 8 + i;
            float d2 = sqa + ssq[b] - 2.0f * sg[a * 33 + b];
            float dm = (d2 > 0.0f) ? sqrtf(d2) : 0.0f;
            part = fmaf(selw[b], dm, part);
        }
        part += __shfl_down_sync(0xffffffffu, part, 2);
        part += __shfl_down_sync(0xffffffffu, part, 1);
        if (q == 0) sdist[a] = part;
    }
    __syncthreads();

    // --- softmax(-dist) * tw, renormalized (warp 0 only) ---
    if (tid < 32) {
        float v = sdist[tid];
        float m = v;
#pragma unroll
        for (int off = 16; off; off >>= 1)
            m = fminf(m, __shfl_xor_sync(0xffffffffu, m, off));
        float r = expf(m - v) * selw[tid];
        float s = r;
#pragma unroll
        for (int off = 16; off; off >>= 1)
            s += __shfl_xor_sync(0xffffffffu, s, off);
        srel[tid] = r / s;
    }
    __syncthreads();

    // --- out[d] = bias[d] + sum_k rel[k] * xi[k][d] ---
    {
        float acc = bias[tid];
#pragma unroll
        for (int k = 0; k < 32; ++k)
            acc = fmaf(srel[k], sxi[k * PITCH + tid], acc);
        out[(size_t)node * DOUT + tid] = acc;
    }
}

// ---------------------------------------------------------------------------
// Launch
// ---------------------------------------------------------------------------
extern "C" void kernel_launch(void* const* d_in, const int* in_sizes, int n_in,
                              void* d_out, int out_size)
{
    const float* feat   = (const float*)d_in[0];   // [n, 128]
    const float* ew     = (const float*)d_in[1];   // [n, 48]
    const float* weight = (const float*)d_in[2];   // [128, 128]
    const float* bias   = (const float*)d_in[3];   // [128]
    const int*   nbr    = (const int*)  d_in[4];   // [n, 48] int32
    float*       out    = (float*)d_out;

    int n = in_sizes[0] / DIN;                     // 50000

    gemm_kernel<<<(n + 127) / 128, 256>>>(feat, weight, n);
    node_kernel<<<n, 128>>>(ew, nbr, bias, out, n);
}

// round 4
// speedup vs baseline: 2.2174x; 1.6270x over previous
#include <cuda_runtime.h>
#include <cuda_bf16.h>
#include <cstdint>

// Problem constants
#define DIN   128
#define DOUT  128
#define DEG   48
#define KSEL  32
#define NPAD  50048

__device__ float g_x[(size_t)NPAD * DOUT];

#define FMA2(d, a, b, c) \
    asm("fma.rn.f32x2 %0, %1, %2, %3;" : "=l"(d) : "l"(a), "l"(b), "l"(c))

// ---------------------------------------------------------------------------
// Kernel A: x = feat @ W   (register-tiled SGEMM, f32x2) — unchanged
// ---------------------------------------------------------------------------
__global__ __launch_bounds__(256) void gemm_kernel(const float* __restrict__ feat,
                                                   const float* __restrict__ W,
                                                   int n)
{
    __shared__ __align__(16) float As[16][132];
    __shared__ __align__(16) float Bs[16][128];

    const int tid  = threadIdx.x;
    const int tx   = tid & 15;
    const int ty   = tid >> 4;
    const int row0 = blockIdx.x * 128;

    unsigned long long acc2[8][4];
#pragma unroll
    for (int i = 0; i < 8; ++i)
#pragma unroll
        for (int j = 0; j < 4; ++j) acc2[i][j] = 0ull;

    for (int kk = 0; kk < 128; kk += 16) {
#pragma unroll
        for (int it = 0; it < 2; ++it) {
            int r  = tid & 127;
            int kq = (tid >> 7) + it * 2;
            int rg = row0 + r;
            if (rg > n - 1) rg = n - 1;
            float4 v = *(const float4*)&feat[(size_t)rg * DIN + kk + kq * 4];
            As[kq * 4 + 0][r] = v.x;
            As[kq * 4 + 1][r] = v.y;
            As[kq * 4 + 2][r] = v.z;
            As[kq * 4 + 3][r] = v.w;
        }
#pragma unroll
        for (int it = 0; it < 2; ++it) {
            int idx = tid + it * 256;
            int kl  = idx >> 5;
            int c4  = idx & 31;
            *(float4*)&Bs[kl][c4 * 4] =
                *(const float4*)&W[(size_t)(kk + kl) * DOUT + c4 * 4];
        }
        __syncthreads();

#pragma unroll
        for (int k = 0; k < 16; ++k) {
            float a[8];
            *(float4*)&a[0] = *(const float4*)&As[k][ty * 8];
            *(float4*)&a[4] = *(const float4*)&As[k][ty * 8 + 4];
            ulonglong2 b01 = *(const ulonglong2*)&Bs[k][tx * 8];
            ulonglong2 b23 = *(const ulonglong2*)&Bs[k][tx * 8 + 4];
#pragma unroll
            for (int i = 0; i < 8; ++i) {
                unsigned long long ai;
                asm("mov.b64 %0, {%1, %1};" : "=l"(ai) : "f"(a[i]));
                FMA2(acc2[i][0], ai, b01.x, acc2[i][0]);
                FMA2(acc2[i][1], ai, b01.y, acc2[i][1]);
                FMA2(acc2[i][2], ai, b23.x, acc2[i][2]);
                FMA2(acc2[i][3], ai, b23.y, acc2[i][3]);
            }
        }
        __syncthreads();
    }

#pragma unroll
    for (int i = 0; i < 8; ++i) {
        int rg = row0 + ty * 8 + i;
        float o[8];
#pragma unroll
        for (int j = 0; j < 4; ++j)
            asm("mov.b64 {%0, %1}, %2;" : "=f"(o[2 * j]), "=f"(o[2 * j + 1]) : "l"(acc2[i][j]));
        *(float4*)&g_x[(size_t)rg * DOUT + tx * 8 + 0] = *(float4*)&o[0];
        *(float4*)&g_x[(size_t)rg * DOUT + tx * 8 + 4] = *(float4*)&o[4];
    }
}

// ---------------------------------------------------------------------------
// Kernel B: per-node top-k, Gram via mma.sync bf16 split (3-pass), softmax, agg
// 1 CTA per node, 128 threads (4 warps in 2x2 grid over the 32x32 Gram)
// ---------------------------------------------------------------------------

#define BPITCH 136   // bf16 row pitch (272 B): 17*16B -> ldmatrix conflict-free
#define GPITCH 34    // gram pitch (even -> float2 stores)

__device__ __forceinline__ uint32_t smem_u32(const void* p) {
    uint32_t a;
    asm("{ .reg .u64 t; cvta.to.shared.u64 t, %1; cvt.u32.u64 %0, t; }" : "=r"(a) : "l"(p));
    return a;
}

__device__ __forceinline__ void ldmatrix_x4(uint32_t* r, uint32_t addr) {
    asm volatile("ldmatrix.sync.aligned.m8n8.x4.shared.b16 {%0,%1,%2,%3}, [%4];"
                 : "=r"(r[0]), "=r"(r[1]), "=r"(r[2]), "=r"(r[3]) : "r"(addr));
}

__device__ __forceinline__ void mma_bf16(float* c, const uint32_t* a, const uint32_t* b) {
    asm volatile(
        "mma.sync.aligned.m16n8k16.row.col.f32.bf16.bf16.f32 "
        "{%0,%1,%2,%3}, {%4,%5,%6,%7}, {%8,%9}, {%0,%1,%2,%3};"
        : "+f"(c[0]), "+f"(c[1]), "+f"(c[2]), "+f"(c[3])
        : "r"(a[0]), "r"(a[1]), "r"(a[2]), "r"(a[3]), "r"(b[0]), "r"(b[1]));
}

__global__ __launch_bounds__(128) void node_kernel(const float* __restrict__ ew,
                                                   const int*   __restrict__ nbr,
                                                   const float* __restrict__ bias,
                                                   float*       __restrict__ out,
                                                   int n)
{
    __shared__ __align__(16) __nv_bfloat16 xhi[32 * BPITCH];  // 8704 B
    __shared__ __align__(16) __nv_bfloat16 xlo[32 * BPITCH];  // 8704 B
    __shared__ __align__(16) float sg[32 * GPITCH];           // 4352 B
    __shared__ float sw49[52];
    __shared__ int   sid49[52];
    __shared__ float selw[32];
    __shared__ int   selid[32];
    __shared__ float ssq[32];
    __shared__ float sdist[32];
    __shared__ float srel[32];

    const int node = blockIdx.x;
    const int tid  = threadIdx.x;
    const int lane = tid & 31;
    const int wrp  = tid >> 5;

    // --- load 48 edges + self-loop ---
    if (tid < DEG) {
        sw49[tid]  = ew[(size_t)node * DEG + tid];
        sid49[tid] = nbr[(size_t)node * DEG + tid];
    } else if (tid == DEG) {
        sw49[DEG]  = 1.0f;
        sid49[DEG] = node;
    }
    __syncthreads();

    // --- top-32 of 49 by weight (stable rank = lax.top_k tie-break) ---
    if (tid < DEG + 1) {
        float v = sw49[tid];
        int rank = 0;
#pragma unroll
        for (int j = 0; j < DEG + 1; ++j) {
            float wj = sw49[j];
            rank += (wj > v) || (wj == v && j < tid);
        }
        if (rank < KSEL) {
            selw[rank]  = v;
            selid[rank] = sid49[tid];
        }
    }
    __syncthreads();

    // --- gather xi rows (coalesced), split to bf16 hi/lo in shared ---
    {
        const int r0 = wrp * 8;
        const int c0 = lane * 4;
#pragma unroll
        for (int r = 0; r < 8; ++r) {
            const int row = r0 + r;
            const int id  = selid[row];
            float4 v = *(const float4*)&g_x[(size_t)id * DOUT + c0];

            __nv_bfloat16 hx = __float2bfloat16_rn(v.x);
            __nv_bfloat16 hy = __float2bfloat16_rn(v.y);
            __nv_bfloat16 hz = __float2bfloat16_rn(v.z);
            __nv_bfloat16 hw = __float2bfloat16_rn(v.w);
            __nv_bfloat16 lx = __float2bfloat16_rn(v.x - __bfloat162float(hx));
            __nv_bfloat16 ly = __float2bfloat16_rn(v.y - __bfloat162float(hy));
            __nv_bfloat16 lz = __float2bfloat16_rn(v.z - __bfloat162float(hz));
            __nv_bfloat16 lw = __float2bfloat16_rn(v.w - __bfloat162float(hw));

            uint2 hp, lp;
            hp.x = (uint32_t)__bfloat16_as_ushort(hx) | ((uint32_t)__bfloat16_as_ushort(hy) << 16);
            hp.y = (uint32_t)__bfloat16_as_ushort(hz) | ((uint32_t)__bfloat16_as_ushort(hw) << 16);
            lp.x = (uint32_t)__bfloat16_as_ushort(lx) | ((uint32_t)__bfloat16_as_ushort(ly) << 16);
            lp.y = (uint32_t)__bfloat16_as_ushort(lz) | ((uint32_t)__bfloat16_as_ushort(lw) << 16);

            *(uint2*)&xhi[row * BPITCH + c0] = hp;
            *(uint2*)&xlo[row * BPITCH + c0] = lp;
        }
    }
    __syncthreads();

    // --- Gram = Xb Xb^T via mma.sync bf16, 3-pass split ---
    // warp grid 2x2: rows m0..m0+15, cols n0..n0+15 (2 n-tiles of 8)
    {
        const int m0 = (wrp & 1) * 16;
        const int n0 = (wrp >> 1) * 16;
        const int rsel = lane >> 3, rin = lane & 7;

        // A-frag source rows/cols (row-major X):
        //   m8n8 matrices in order {m0..m0+7,k0..7},{m0+8..,k0..7},{m0..,k8..15},{m0+8..,k8..15}
        const uint32_t a_off = (uint32_t)((m0 + (rsel & 1) * 8 + rin) * BPITCH
                                          + ((rsel >> 1) * 8)) * 2;
        // B-frag: matrices {n0..n0+7,k0..7},{n0..n0+7,k8..15},{n0+8..,k0..7},{n0+8..,k8..15}
        const uint32_t b_off = (uint32_t)((n0 + (rsel >> 1) * 8 + rin) * BPITCH
                                          + ((rsel & 1) * 8)) * 2;

        const uint32_t hbase = smem_u32(xhi);
        const uint32_t lbase = smem_u32(xlo);

        float c0f[4] = {0.f, 0.f, 0.f, 0.f};
        float c1f[4] = {0.f, 0.f, 0.f, 0.f};

#pragma unroll
        for (int kc = 0; kc < 8; ++kc) {
            const uint32_t kadd = (uint32_t)(kc * 16 * 2);
            uint32_t ah[4], al[4], bh[4], bl[4];
            ldmatrix_x4(ah, hbase + a_off + kadd);
            ldmatrix_x4(al, lbase + a_off + kadd);
            ldmatrix_x4(bh, hbase + b_off + kadd);
            ldmatrix_x4(bl, lbase + b_off + kadd);

            // n-tile 0: b regs {bh[0],bh[1]} / {bl[0],bl[1]}
            mma_bf16(c0f, ah, &bh[0]);
            mma_bf16(c0f, ah, &bl[0]);
            mma_bf16(c0f, al, &bh[0]);
            // n-tile 1: b regs {bh[2],bh[3]} / {bl[2],bl[3]}
            mma_bf16(c1f, ah, &bh[2]);
            mma_bf16(c1f, ah, &bl[2]);
            mma_bf16(c1f, al, &bh[2]);
        }

        // Epilogue: C-frag -> sg.  c0,c1: row=m0+(l>>2), col=n0+8t+2(l&3); c2,c3: row+8
        const int ra = m0 + (lane >> 2);
        const int cb = 2 * (lane & 3);
        *(float2*)&sg[ra * GPITCH + n0 + cb]            = make_float2(c0f[0], c0f[1]);
        *(float2*)&sg[(ra + 8) * GPITCH + n0 + cb]      = make_float2(c0f[2], c0f[3]);
        *(float2*)&sg[ra * GPITCH + n0 + 8 + cb]        = make_float2(c1f[0], c1f[1]);
        *(float2*)&sg[(ra + 8) * GPITCH + n0 + 8 + cb]  = make_float2(c1f[2], c1f[3]);
    }
    __syncthreads();

    if (tid < 32) ssq[tid] = sg[tid * GPITCH + tid];
    __syncthreads();

    // --- weighted medoid distances ---
    {
        int a = tid >> 2, q = tid & 3;
        float sqa  = ssq[a];
        float part = 0.0f;
#pragma unroll
        for (int i = 0; i < 8; ++i) {
            int b = q * 8 + i;
            float d2 = sqa + ssq[b] - 2.0f * sg[a * GPITCH + b];
            float dm = (d2 > 0.0f) ? sqrtf(d2) : 0.0f;
            part = fmaf(selw[b], dm, part);
        }
        part += __shfl_down_sync(0xffffffffu, part, 2);
        part += __shfl_down_sync(0xffffffffu, part, 1);
        if (q == 0) sdist[a] = part;
    }
    __syncthreads();

    // --- softmax(-dist) * tw, renormalized (warp 0) ---
    if (tid < 32) {
        float v = sdist[tid];
        float m = v;
#pragma unroll
        for (int off = 16; off; off >>= 1)
            m = fminf(m, __shfl_xor_sync(0xffffffffu, m, off));
        float r = expf(m - v) * selw[tid];
        float s = r;
#pragma unroll
        for (int off = 16; off; off >>= 1)
            s += __shfl_xor_sync(0xffffffffu, s, off);
        srel[tid] = r / s;
    }
    __syncthreads();

    // --- out[d] = bias[d] + sum_k rel[k] * x[sel[k]][d]  (L1-hit re-gather) ---
    {
        float acc = bias[tid];
#pragma unroll
        for (int k = 0; k < 32; ++k)
            acc = fmaf(srel[k], g_x[(size_t)selid[k] * DOUT + tid], acc);
        out[(size_t)node * DOUT + tid] = acc;
    }
}

// ---------------------------------------------------------------------------
// Launch
// ---------------------------------------------------------------------------
extern "C" void kernel_launch(void* const* d_in, const int* in_sizes, int n_in,
                              void* d_out, int out_size)
{
    const float* feat   = (const float*)d_in[0];
    const float* ew     = (const float*)d_in[1];
    const float* weight = (const float*)d_in[2];
    const float* bias   = (const float*)d_in[3];
    const int*   nbr    = (const int*)  d_in[4];
    float*       out    = (float*)d_out;

    int n = in_sizes[0] / DIN;

    gemm_kernel<<<(n + 127) / 128, 256>>>(feat, weight, n);
    node_kernel<<<n, 128>>>(ew, nbr, bias, out, n);
}

// round 5
// speedup vs baseline: 2.2574x; 1.0180x over previous
#include <cuda_runtime.h>
#include <cuda_bf16.h>
#include <cstdint>

// Problem constants
#define DIN   128
#define DOUT  128
#define DEG   48
#define KSEL  32
#define NPAD  50048

__device__ float g_x[(size_t)NPAD * DOUT];
__device__ __nv_bfloat16 g_wThi[128 * 128];   // W^T hi, [n][k]
__device__ __nv_bfloat16 g_wTlo[128 * 128];   // W^T lo, [n][k]

// ---------------------------------------------------------------------------
// Common helpers
// ---------------------------------------------------------------------------
__device__ __forceinline__ uint32_t smem_u32(const void* p) {
    uint32_t a;
    asm("{ .reg .u64 t; cvta.to.shared.u64 t, %1; cvt.u32.u64 %0, t; }" : "=r"(a) : "l"(p));
    return a;
}

__device__ __forceinline__ void ldmatrix_x4(uint32_t* r, uint32_t addr) {
    asm volatile("ldmatrix.sync.aligned.m8n8.x4.shared.b16 {%0,%1,%2,%3}, [%4];"
                 : "=r"(r[0]), "=r"(r[1]), "=r"(r[2]), "=r"(r[3]) : "r"(addr));
}

__device__ __forceinline__ void mma_bf16(float* c, const uint32_t* a, const uint32_t* b) {
    asm volatile(
        "mma.sync.aligned.m16n8k16.row.col.f32.bf16.bf16.f32 "
        "{%0,%1,%2,%3}, {%4,%5,%6,%7}, {%8,%9}, {%0,%1,%2,%3};"
        : "+f"(c[0]), "+f"(c[1]), "+f"(c[2]), "+f"(c[3])
        : "r"(a[0]), "r"(a[1]), "r"(a[2]), "r"(a[3]), "r"(b[0]), "r"(b[1]));
}

// Truncation split: hi = top-16 bits of fp32 (as bf16), lo = rn-bf16 of (x - hi).
// hi-pair in 1 PRMT, lo-pair in 1 packed cvt.
__device__ __forceinline__ void split4(float4 v, uint2& hp, uint2& lp) {
    uint32_t ax = __float_as_uint(v.x), ay = __float_as_uint(v.y);
    uint32_t az = __float_as_uint(v.z), aw = __float_as_uint(v.w);
    hp.x = __byte_perm(ax, ay, 0x7632);
    hp.y = __byte_perm(az, aw, 0x7632);
    float lx = v.x - __uint_as_float(ax & 0xffff0000u);
    float ly = v.y - __uint_as_float(ay & 0xffff0000u);
    float lz = v.z - __uint_as_float(az & 0xffff0000u);
    float lw = v.w - __uint_as_float(aw & 0xffff0000u);
    asm("cvt.rn.bf16x2.f32 %0, %1, %2;" : "=r"(lp.x) : "f"(ly), "f"(lx));
    asm("cvt.rn.bf16x2.f32 %0, %1, %2;" : "=r"(lp.y) : "f"(lw), "f"(lz));
}

// ---------------------------------------------------------------------------
// Kernel 0: transpose + split W -> g_wThi/g_wTlo  ([n][k] bf16)
// ---------------------------------------------------------------------------
__global__ __launch_bounds__(256) void wsplit_kernel(const float* __restrict__ W)
{
    int idx = blockIdx.x * 256 + threadIdx.x;     // 0..16383
    int k = idx >> 7, nn = idx & 127;
    float v = W[k * 128 + nn];                    // coalesced read
    uint32_t b = __float_as_uint(v);
    uint32_t hbits = b & 0xffff0000u;
    float lo = v - __uint_as_float(hbits);
    g_wThi[nn * 128 + k] = __ushort_as_bfloat16((unsigned short)(hbits >> 16));
    g_wTlo[nn * 128 + k] = __float2bfloat16_rn(lo);
}

// ---------------------------------------------------------------------------
// Kernel A: x = feat @ W via bf16 3-pass mma.sync
// CTA: 256 thr (8 warps, grid 2Mx4N -> 64x32 per warp), M-tile 128, k-chunk 32
// ---------------------------------------------------------------------------
#define GAP 40   // bf16 smem pitch per 32-k chunk row (80 B = 5*16B, ldmatrix conflict-free)

__global__ __launch_bounds__(256) void gemm_kernel(const float* __restrict__ feat,
                                                   int n)
{
    __shared__ __align__(16) __nv_bfloat16 sa_h[128 * GAP];
    __shared__ __align__(16) __nv_bfloat16 sa_l[128 * GAP];
    __shared__ __align__(16) __nv_bfloat16 sb_h[128 * GAP];
    __shared__ __align__(16) __nv_bfloat16 sb_l[128 * GAP];

    const int tid  = threadIdx.x;
    const int lane = tid & 31;
    const int wrp  = tid >> 5;
    const int row0 = blockIdx.x * 128;

    const int m0 = (wrp & 1) * 64;
    const int n0 = (wrp >> 1) * 32;
    const int rsel = lane >> 3, rin = lane & 7;

    const uint32_t sah = smem_u32(sa_h), sal = smem_u32(sa_l);
    const uint32_t sbh = smem_u32(sb_h), sbl = smem_u32(sb_l);

    float acc[4][4][4];
#pragma unroll
    for (int mt = 0; mt < 4; ++mt)
#pragma unroll
        for (int nt = 0; nt < 4; ++nt)
#pragma unroll
            for (int i = 0; i < 4; ++i) acc[mt][nt][i] = 0.0f;

    for (int kt = 0; kt < 4; ++kt) {
        // load A chunk: feat[row0..row0+128)[kt*32..+32), split to bf16 hi/lo
#pragma unroll
        for (int i = 0; i < 4; ++i) {
            int idx = tid + i * 256;              // 0..1023
            int r = idx >> 3, q = idx & 7;
            int rg = row0 + r; if (rg > n - 1) rg = n - 1;
            float4 v = *(const float4*)&feat[(size_t)rg * DIN + kt * 32 + q * 4];
            uint2 hp, lp;
            split4(v, hp, lp);
            *(uint2*)&sa_h[r * GAP + q * 4] = hp;
            *(uint2*)&sa_l[r * GAP + q * 4] = lp;
        }
        // load B chunk: wT[n][kt*32..+32) bf16 (pre-split)
#pragma unroll
        for (int i = 0; i < 2; ++i) {
            int idx = tid + i * 256;              // 0..511
            int r = idx >> 2, q = idx & 3;
            *(uint4*)&sb_h[r * GAP + q * 8] =
                *(const uint4*)&g_wThi[r * 128 + kt * 32 + q * 8];
            *(uint4*)&sb_l[r * GAP + q * 8] =
                *(const uint4*)&g_wTlo[r * 128 + kt * 32 + q * 8];
        }
        __syncthreads();

#pragma unroll
        for (int kc = 0; kc < 2; ++kc) {
            const uint32_t kadd = kc * 32;        // 16 bf16 = 32 B
            uint32_t bh[8], bl[8];
#pragma unroll
            for (int h = 0; h < 2; ++h) {
                uint32_t boff = (uint32_t)((n0 + h * 16 + (rsel >> 1) * 8 + rin) * GAP
                                           + (rsel & 1) * 8) * 2 + kadd;
                ldmatrix_x4(&bh[h * 4], sbh + boff);
                ldmatrix_x4(&bl[h * 4], sbl + boff);
            }
#pragma unroll
            for (int mt = 0; mt < 4; ++mt) {
                uint32_t aoff = (uint32_t)((m0 + mt * 16 + (rsel & 1) * 8 + rin) * GAP
                                           + (rsel >> 1) * 8) * 2 + kadd;
                uint32_t ah[4], al[4];
                ldmatrix_x4(ah, sah + aoff);
                ldmatrix_x4(al, sal + aoff);
#pragma unroll
                for (int nt = 0; nt < 4; ++nt) {
                    mma_bf16(acc[mt][nt], ah, &bh[nt * 2]);
                    mma_bf16(acc[mt][nt], ah, &bl[nt * 2]);
                    mma_bf16(acc[mt][nt], al, &bh[nt * 2]);
                }
            }
        }
        __syncthreads();
    }

    // epilogue: C-frags -> g_x (padded rows OK)
#pragma unroll
    for (int mt = 0; mt < 4; ++mt) {
        int ra = row0 + m0 + mt * 16 + (lane >> 2);
#pragma unroll
        for (int nt = 0; nt < 4; ++nt) {
            int cb = n0 + nt * 8 + 2 * (lane & 3);
            *(float2*)&g_x[(size_t)ra * DOUT + cb] =
                make_float2(acc[mt][nt][0], acc[mt][nt][1]);
            *(float2*)&g_x[(size_t)(ra + 8) * DOUT + cb] =
                make_float2(acc[mt][nt][2], acc[mt][nt][3]);
        }
    }
}

// ---------------------------------------------------------------------------
// Kernel B: per-node top-k, Gram via 2-pass symmetrized bf16 mma, softmax, agg
// 1 CTA per node, 128 threads (4 warps, 2x2 grid over 32x32 Gram)
// ---------------------------------------------------------------------------
#define BPITCH 136   // bf16 row pitch (272 B), ldmatrix conflict-free
#define GPITCH 34

__global__ __launch_bounds__(128) void node_kernel(const float* __restrict__ ew,
                                                   const int*   __restrict__ nbr,
                                                   const float* __restrict__ bias,
                                                   float*       __restrict__ out,
                                                   int n)
{
    __shared__ __align__(16) __nv_bfloat16 xhi[32 * BPITCH];
    __shared__ __align__(16) __nv_bfloat16 xlo[32 * BPITCH];
    __shared__ __align__(16) float sghh[32 * GPITCH];   // hi.hi^T
    __shared__ __align__(16) float sghl[32 * GPITCH];   // hi.lo^T
    __shared__ float sw49[52];
    __shared__ int   sid49[52];
    __shared__ float selw[32];
    __shared__ int   selid[32];
    __shared__ float ssq[32];
    __shared__ float sdist[32];
    __shared__ float srel[32];

    const int node = blockIdx.x;
    const int tid  = threadIdx.x;
    const int lane = tid & 31;
    const int wrp  = tid >> 5;

    // --- load 48 edges + self-loop ---
    if (tid < DEG) {
        sw49[tid]  = ew[(size_t)node * DEG + tid];
        sid49[tid] = nbr[(size_t)node * DEG + tid];
    } else if (tid == DEG) {
        sw49[DEG]  = 1.0f;
        sid49[DEG] = node;
    }
    __syncthreads();

    // --- top-32 of 49 (stable rank = lax.top_k tie-break) ---
    if (tid < DEG + 1) {
        float v = sw49[tid];
        int rank = 0;
#pragma unroll
        for (int j = 0; j < DEG + 1; ++j) {
            float wj = sw49[j];
            rank += (wj > v) || (wj == v && j < tid);
        }
        if (rank < KSEL) {
            selw[rank]  = v;
            selid[rank] = sid49[tid];
        }
    }
    __syncthreads();

    // --- gather xi rows (coalesced), truncation-split to bf16 hi/lo ---
    {
        const int r0 = wrp * 8;
        const int c0 = lane * 4;
#pragma unroll
        for (int r = 0; r < 8; ++r) {
            const int row = r0 + r;
            const int id  = selid[row];
            float4 v = *(const float4*)&g_x[(size_t)id * DOUT + c0];
            uint2 hp, lp;
            split4(v, hp, lp);
            *(uint2*)&xhi[row * BPITCH + c0] = hp;
            *(uint2*)&xlo[row * BPITCH + c0] = lp;
        }
    }
    __syncthreads();

    // --- Gram 2-pass: C_hh = hi.hi^T, C_hl = hi.lo^T ---
    {
        const int m0 = (wrp & 1) * 16;
        const int n0 = (wrp >> 1) * 16;
        const int rsel = lane >> 3, rin = lane & 7;

        const uint32_t a_off = (uint32_t)((m0 + (rsel & 1) * 8 + rin) * BPITCH
                                          + ((rsel >> 1) * 8)) * 2;
        const uint32_t b_off = (uint32_t)((n0 + (rsel >> 1) * 8 + rin) * BPITCH
                                          + ((rsel & 1) * 8)) * 2;

        const uint32_t hbase = smem_u32(xhi);
        const uint32_t lbase = smem_u32(xlo);

        float chh0[4] = {0.f, 0.f, 0.f, 0.f};
        float chl0[4] = {0.f, 0.f, 0.f, 0.f};
        float chh1[4] = {0.f, 0.f, 0.f, 0.f};
        float chl1[4] = {0.f, 0.f, 0.f, 0.f};

#pragma unroll
        for (int kc = 0; kc < 8; ++kc) {
            const uint32_t kadd = (uint32_t)(kc * 32);
            uint32_t ah[4], bh[4], bl[4];
            ldmatrix_x4(ah, hbase + a_off + kadd);
            ldmatrix_x4(bh, hbase + b_off + kadd);
            ldmatrix_x4(bl, lbase + b_off + kadd);

            mma_bf16(chh0, ah, &bh[0]);
            mma_bf16(chl0, ah, &bl[0]);
            mma_bf16(chh1, ah, &bh[2]);
            mma_bf16(chl1, ah, &bl[2]);
        }

        const int ra = m0 + (lane >> 2);
        const int cb = 2 * (lane & 3);
        *(float2*)&sghh[ra * GPITCH + n0 + cb]           = make_float2(chh0[0], chh0[1]);
        *(float2*)&sghh[(ra + 8) * GPITCH + n0 + cb]     = make_float2(chh0[2], chh0[3]);
        *(float2*)&sghh[ra * GPITCH + n0 + 8 + cb]       = make_float2(chh1[0], chh1[1]);
        *(float2*)&sghh[(ra + 8) * GPITCH + n0 + 8 + cb] = make_float2(chh1[2], chh1[3]);
        *(float2*)&sghl[ra * GPITCH + n0 + cb]           = make_float2(chl0[0], chl0[1]);
        *(float2*)&sghl[(ra + 8) * GPITCH + n0 + cb]     = make_float2(chl0[2], chl0[3]);
        *(float2*)&sghl[ra * GPITCH + n0 + 8 + cb]       = make_float2(chl1[0], chl1[1]);
        *(float2*)&sghl[(ra + 8) * GPITCH + n0 + 8 + cb] = make_float2(chl1[2], chl1[3]);
    }
    __syncthreads();

    // gram[a][b] = hh[a][b] + hl[a][b] + hl[b][a];  ssq = diagonal
    if (tid < 32)
        ssq[tid] = sghh[tid * GPITCH + tid] + 2.0f * sghl[tid * GPITCH + tid];
    __syncthreads();

    // --- weighted medoid distances ---
    {
        int a = tid >> 2, q = tid & 3;
        float sqa  = ssq[a];
        float part = 0.0f;
#pragma unroll
        for (int i = 0; i < 8; ++i) {
            int b = q * 8 + i;
            float g = sghh[a * GPITCH + b] + sghl[a * GPITCH + b] + sghl[b * GPITCH + a];
            float d2 = sqa + ssq[b] - 2.0f * g;
            float dm = (d2 > 0.0f) ? sqrtf(d2) : 0.0f;
            part = fmaf(selw[b], dm, part);
        }
        part += __shfl_down_sync(0xffffffffu, part, 2);
        part += __shfl_down_sync(0xffffffffu, part, 1);
        if (q == 0) sdist[a] = part;
    }
    __syncthreads();

    // --- softmax(-dist) * tw, renormalized (warp 0) ---
    if (tid < 32) {
        float v = sdist[tid];
        float m = v;
#pragma unroll
        for (int off = 16; off; off >>= 1)
            m = fminf(m, __shfl_xor_sync(0xffffffffu, m, off));
        float r = expf(m - v) * selw[tid];
        float s = r;
#pragma unroll
        for (int off = 16; off; off >>= 1)
            s += __shfl_xor_sync(0xffffffffu, s, off);
        srel[tid] = r / s;
    }
    __syncthreads();

    // --- out[d] = bias[d] + sum_k rel[k] * x[sel[k]][d]  (L1-hit re-gather) ---
    {
        float acc = bias[tid];
#pragma unroll
        for (int k = 0; k < 32; ++k)
            acc = fmaf(srel[k], g_x[(size_t)selid[k] * DOUT + tid], acc);
        out[(size_t)node * DOUT + tid] = acc;
    }
}

// ---------------------------------------------------------------------------
// Launch
// ---------------------------------------------------------------------------
extern "C" void kernel_launch(void* const* d_in, const int* in_sizes, int n_in,
                              void* d_out, int out_size)
{
    const float* feat   = (const float*)d_in[0];
    const float* ew     = (const float*)d_in[1];
    const float* weight = (const float*)d_in[2];
    const float* bias   = (const float*)d_in[3];
    const int*   nbr    = (const int*)  d_in[4];
    float*       out    = (float*)d_out;

    int n = in_sizes[0] / DIN;

    wsplit_kernel<<<64, 256>>>(weight);
    gemm_kernel<<<(n + 127) / 128, 256>>>(feat, n);
    node_kernel<<<n, 128>>>(ew, nbr, bias, out, n);
}